// round 5
// baseline (speedup 1.0000x reference)
#include <cuda_runtime.h>
#include <cuda_bf16.h>
#include <math.h>
#include <stdint.h>

// Problem constants (fixed shapes from reference setup_inputs)
#define NTOK   8192      // B*S = 2*4096
#define SEQ    4096
#define DMODEL 1024
#define NEXP   16
#define DBOT   256
#define DTASK  32
#define RQUOTA 64

#define SA 40            // smem row stride in bf16 elems (80B, conflict-free)
#define BUFB 40960       // bytes per smem stage (4 arrays * 128*40*2)
#define OFF_AL 10240
#define OFF_BH 20480
#define OFF_BL 30720

// ================= device scratch =================
__device__ float  g_H[NTOK * DBOT];
__device__ float  g_L[NTOK * NEXP];
__device__ float  g_gmask[NEXP * DBOT];
__device__ float  g_cs[NEXP];
__device__ float  g_base[2 * NEXP];
__device__ float  g_stats[4];
__device__ double g_part[2 * 64 * 2];
__device__ int    g_sel[NTOK * 2];
__device__ float  g_w[NTOK * 2];
// pre-split activations
__device__ __align__(16) __nv_bfloat16 g_Xh[NTOK * DMODEL];
__device__ __align__(16) __nv_bfloat16 g_Xl[NTOK * DMODEL];
__device__ __align__(16) __nv_bfloat16 g_Zh[NTOK * DBOT];
__device__ __align__(16) __nv_bfloat16 g_Zl[NTOK * DBOT];
// combined GEMM1 B: rows 0..255 = W_down^T, 256..271 = Wr[:D]^T, 272..383 zero
__device__ __align__(16) __nv_bfloat16 g_B1T_h[384 * DMODEL];
__device__ __align__(16) __nv_bfloat16 g_B1T_l[384 * DMODEL];
// GEMM2 B: W_up^T [1024][256]
__device__ __align__(16) __nv_bfloat16 g_B2T_h[DMODEL * DBOT];
__device__ __align__(16) __nv_bfloat16 g_B2T_l[DMODEL * DBOT];

// ================= helpers =================
__device__ __forceinline__ uint32_t smem_u32(const void* p) {
    uint32_t a;
    asm("{ .reg .u64 t; cvta.to.shared.u64 t, %1; cvt.u32.u64 %0, t; }" : "=r"(a) : "l"(p));
    return a;
}
__device__ __forceinline__ void cp16(uint32_t dst, const void* src) {
    asm volatile("cp.async.cg.shared.global [%0], [%1], 16;" :: "r"(dst), "l"(src));
}
#define CP_COMMIT() asm volatile("cp.async.commit_group;" ::: "memory")
#define CP_WAIT(n)  asm volatile("cp.async.wait_group %0;" :: "n"(n) : "memory")

#define LDSM4(d, addr) \
    asm volatile("ldmatrix.sync.aligned.m8n8.x4.shared.b16 {%0,%1,%2,%3}, [%4];" \
        : "=r"((d)[0]), "=r"((d)[1]), "=r"((d)[2]), "=r"((d)[3]) : "r"(addr))

__device__ __forceinline__ void mma16816(float* d, const uint32_t* a,
                                         const uint32_t* b) {
    asm volatile(
        "mma.sync.aligned.m16n8k16.row.col.f32.bf16.bf16.f32 "
        "{%0,%1,%2,%3}, {%4,%5,%6,%7}, {%8,%9}, {%0,%1,%2,%3};"
        : "+f"(d[0]), "+f"(d[1]), "+f"(d[2]), "+f"(d[3])
        : "r"(a[0]), "r"(a[1]), "r"(a[2]), "r"(a[3]), "r"(b[0]), "r"(b[1]));
}

__device__ __forceinline__ void split2(float x, float y, uint32_t& h, uint32_t& l) {
    __nv_bfloat162 hh = __float22bfloat162_rn(make_float2(x, y));
    float rx = x - __bfloat162float(hh.x);
    float ry = y - __bfloat162float(hh.y);
    __nv_bfloat162 ll = __float22bfloat162_rn(make_float2(rx, ry));
    h = *reinterpret_cast<uint32_t*>(&hh);
    l = *reinterpret_cast<uint32_t*>(&ll);
}

// ================= kernel 1: stats partials + x split =================
__global__ void k_stats(const float* __restrict__ x) {
    int b = blockIdx.y;
    const float4* xb = reinterpret_cast<const float4*>(x + (size_t)b * SEQ * DMODEL);
    uint2* xh = reinterpret_cast<uint2*>(g_Xh + (size_t)b * SEQ * DMODEL);
    uint2* xl = reinterpret_cast<uint2*>(g_Xl + (size_t)b * SEQ * DMODEL);
    const int nvec = SEQ * DMODEL / 4;
    double s = 0.0, q = 0.0;
    for (int i = blockIdx.x * blockDim.x + threadIdx.x; i < nvec;
         i += gridDim.x * blockDim.x) {
        float4 v = xb[i];
        s += (double)v.x; q += (double)v.x * v.x;
        s += (double)v.y; q += (double)v.y * v.y;
        s += (double)v.z; q += (double)v.z * v.z;
        s += (double)v.w; q += (double)v.w * v.w;
        uint32_t h0, l0, h1, l1;
        split2(v.x, v.y, h0, l0);
        split2(v.z, v.w, h1, l1);
        xh[i] = make_uint2(h0, h1);
        xl[i] = make_uint2(l0, l1);
    }
    __shared__ double rs[256], rq[256];
    rs[threadIdx.x] = s; rq[threadIdx.x] = q;
    __syncthreads();
    for (int st = 128; st > 0; st >>= 1) {
        if (threadIdx.x < st) {
            rs[threadIdx.x] += rs[threadIdx.x + st];
            rq[threadIdx.x] += rq[threadIdx.x + st];
        }
        __syncthreads();
    }
    if (threadIdx.x == 0) {
        g_part[(b * 64 + blockIdx.x) * 2 + 0] = rs[0];
        g_part[(b * 64 + blockIdx.x) * 2 + 1] = rq[0];
    }
}

// ================= kernel 2: finalize stats, router constants, topo masks =================
__global__ void k_setup(const int* __restrict__ task_id,
                        const float* __restrict__ task_emb,
                        const float* __restrict__ Wr,
                        const float* __restrict__ br,
                        const float* __restrict__ topo) {
    int tid = threadIdx.x;
    __shared__ double rd[256];

    for (int b = 0; b < 2; b++) {
        double s = (tid < 64) ? g_part[(b * 64 + tid) * 2 + 0] : 0.0;
        double q = (tid < 64) ? g_part[(b * 64 + tid) * 2 + 1] : 0.0;
        rd[tid] = s; __syncthreads();
        for (int st = 128; st > 0; st >>= 1) {
            if (tid < st) rd[tid] += rd[tid + st];
            __syncthreads();
        }
        double S = rd[0]; __syncthreads();
        rd[tid] = q; __syncthreads();
        for (int st = 128; st > 0; st >>= 1) {
            if (tid < st) rd[tid] += rd[tid + st];
            __syncthreads();
        }
        double Q = rd[0]; __syncthreads();
        if (tid == 0) {
            const double cnt = (double)SEQ * DMODEL;
            double mu  = S / cnt;
            double var = Q / cnt - mu * mu;
            g_stats[b * 2 + 0] = (float)mu;
            g_stats[b * 2 + 1] = (float)(1.0 / sqrt(var + 1e-5));
        }
        __syncthreads();
    }

    {
        __shared__ float rf[256];
        int e = tid & 15, lane = tid >> 4;
        float p = 0.f;
        for (int d = lane; d < DMODEL; d += 16) p += Wr[d * NEXP + e];
        rf[tid] = p; __syncthreads();
        if (tid < 16) {
            float s2 = 0.f;
            for (int l = 0; l < 16; l++) s2 += rf[l * 16 + tid];
            g_cs[tid] = s2;
        }
        __syncthreads();
    }

    if (tid < 32) {
        int b = tid >> 4, e = tid & 15;
        int tI = task_id[b];
        float v = br[e];
        for (int t = 0; t < DTASK; t++)
            v += task_emb[tI * DTASK + t] * Wr[(DMODEL + t) * NEXP + e];
        g_base[b * NEXP + e] = v;
    }
    __syncthreads();

    __shared__ float row[256];
    __shared__ float rs[256];
    for (int e = 0; e < NEXP; e++) {
        row[tid] = topo[e * DBOT + tid];
        __syncthreads();
        float v = row[tid];
        int rank = 0;
        for (int i = 0; i < DBOT; i++) {
            float u = row[i];
            rank += (u > v) || (u == v && i < tid);
        }
        int sel = (rank < RQUOTA);
        rs[tid] = sel ? 1.f / (1.f + expf(-v)) : 0.f;
        __syncthreads();
        for (int st = 128; st > 0; st >>= 1) {
            if (tid < st) rs[tid] += rs[tid + st];
            __syncthreads();
        }
        float gate = rs[0] / (float)RQUOTA;
        g_gmask[e * DBOT + tid] = sel ? gate : 0.f;
        __syncthreads();
    }
}

// ================= transpose + bf16-split weights =================
__global__ void k_tsplit(const float* __restrict__ in, int R, int C, int sel) {
    __nv_bfloat16* outh;
    __nv_bfloat16* outl;
    if (sel == 0)      { outh = g_B1T_h;                outl = g_B1T_l; }
    else if (sel == 1) { outh = g_B1T_h + 256 * DMODEL; outl = g_B1T_l + 256 * DMODEL; }
    else               { outh = g_B2T_h;                outl = g_B2T_l; }

    __shared__ float t[32][33];
    int c0 = blockIdx.x * 32, r0 = blockIdx.y * 32;
    int tx = threadIdx.x, ty = threadIdx.y;
#pragma unroll
    for (int i = 0; i < 32; i += 8) {
        int r = r0 + ty + i, c = c0 + tx;
        t[ty + i][tx] = (r < R && c < C) ? in[(size_t)r * C + c] : 0.f;
    }
    __syncthreads();
#pragma unroll
    for (int i = 0; i < 32; i += 8) {
        int c = c0 + ty + i, r = r0 + tx;
        if (c < C && r < R) {
            float v = t[tx][ty + i];
            __nv_bfloat16 h = __float2bfloat16(v);
            __nv_bfloat16 l = __float2bfloat16(v - __bfloat162float(h));
            outh[(size_t)c * R + r] = h;
            outl[(size_t)c * R + r] = l;
        }
    }
}

// ================= tensor GEMM core: cp.async 2-stage, ldmatrix, 3-term bf16 =================
// C[row0:+128, n0:+128] = A @ B^T (A [M][K] h/l, B [N][K] h/l)
// MODE 0: plain store (C, ldc). MODE 1: GEMM1 scatter (g_H <256, g_L 256..271)
template <int MODE>
__device__ __forceinline__ void gemm_body(
    const __nv_bfloat16* __restrict__ Ah, const __nv_bfloat16* __restrict__ Al,
    const __nv_bfloat16* __restrict__ Bh, const __nv_bfloat16* __restrict__ Bl,
    int K, int n0, int row0, float* __restrict__ C, int ldc)
{
    extern __shared__ char smem[];
    const int tid = threadIdx.x;
    const int wid = tid >> 5, lane = tid & 31;
    const int wm = wid >> 2, wn = wid & 3;    // 2x4 warp grid
    const bool active = (MODE == 0) || (n0 + wn * 32 < 272);

    float acc[4][4][4] = {};

    const int r4 = tid >> 2, j4 = tid & 3;    // cp.async fill: 64 rows/pass, 2 passes
    const uint32_t sb = smem_u32(smem);
    const uint32_t a_off = ((wm * 64 + (lane & 15)) * SA + (lane >> 4) * 8) * 2;
    const uint32_t b_off = ((wn * 32 + (lane >> 4) * 8 + (lane & 7)) * SA
                            + ((lane >> 3) & 1) * 8) * 2;
    const int nch = K >> 5;

#define ISSUE(ch) do { \
    const uint32_t _db = sb + ((ch) & 1) * BUFB; \
    const int _k0 = (ch) * 32; \
    _Pragma("unroll") \
    for (int p = 0; p < 2; p++) { \
        uint32_t d = _db + ((p * 64 + r4) * 5 + j4) * 16; \
        size_t ai = (size_t)(row0 + p * 64 + r4) * K + _k0 + j4 * 8; \
        cp16(d, Ah + ai); \
        cp16(d + OFF_AL, Al + ai); \
        size_t bi = (size_t)(n0 + p * 64 + r4) * K + _k0 + j4 * 8; \
        cp16(d + OFF_BH, Bh + bi); \
        cp16(d + OFF_BL, Bl + bi); \
    } \
    CP_COMMIT(); } while (0)

    ISSUE(0);
    ISSUE(1);   // nch >= 8 always

    for (int ch = 0; ch < nch; ch++) {
        if (ch + 1 < nch) { CP_WAIT(1); } else { CP_WAIT(0); }
        __syncthreads();

        if (active) {
            const uint32_t ab = sb + (ch & 1) * BUFB;
#pragma unroll
            for (int ks = 0; ks < 2; ks++) {
                const uint32_t koff = ks * 32;  // 16 elems * 2B
                uint32_t ah[4][4], bb[4][2];
#pragma unroll
                for (int mt = 0; mt < 4; mt++)
                    LDSM4(ah[mt], ab + a_off + mt * (16 * SA * 2) + koff);
#pragma unroll
                for (int p = 0; p < 2; p++)
                    LDSM4(&bb[2 * p][0], ab + OFF_BH + b_off + p * (16 * SA * 2) + koff);
                // Ah * Bh
#pragma unroll
                for (int mt = 0; mt < 4; mt++)
#pragma unroll
                    for (int nt = 0; nt < 4; nt++)
                        mma16816(acc[mt][nt], ah[mt], bb[nt]);
                // Al * Bh (reload Al one m-tile at a time -> only 4 extra regs)
#pragma unroll
                for (int mt = 0; mt < 4; mt++) {
                    uint32_t al4[4];
                    LDSM4(al4, ab + OFF_AL + a_off + mt * (16 * SA * 2) + koff);
#pragma unroll
                    for (int nt = 0; nt < 4; nt++)
                        mma16816(acc[mt][nt], al4, bb[nt]);
                }
                // Ah * Bl (Bl overwrites bb regs)
#pragma unroll
                for (int p = 0; p < 2; p++)
                    LDSM4(&bb[2 * p][0], ab + OFF_BL + b_off + p * (16 * SA * 2) + koff);
#pragma unroll
                for (int mt = 0; mt < 4; mt++)
#pragma unroll
                    for (int nt = 0; nt < 4; nt++)
                        mma16816(acc[mt][nt], ah[mt], bb[nt]);
            }
        }
        __syncthreads();
        if (ch + 2 < nch) ISSUE(ch + 2);
    }
#undef ISSUE

    if (!active) return;
    const int g = lane >> 2, tig = lane & 3;
#pragma unroll
    for (int mt = 0; mt < 4; mt++) {
        int r = row0 + wm * 64 + mt * 16 + g;
#pragma unroll
        for (int nt = 0; nt < 4; nt++) {
            int col = n0 + wn * 32 + nt * 8 + 2 * tig;
            float2 v0 = make_float2(acc[mt][nt][0], acc[mt][nt][1]);
            float2 v1 = make_float2(acc[mt][nt][2], acc[mt][nt][3]);
            if (MODE == 0) {
                *reinterpret_cast<float2*>(&C[(size_t)r * ldc + col]) = v0;
                *reinterpret_cast<float2*>(&C[(size_t)(r + 8) * ldc + col]) = v1;
            } else {
                if (col < DBOT) {
                    *reinterpret_cast<float2*>(&g_H[(size_t)r * DBOT + col]) = v0;
                    *reinterpret_cast<float2*>(&g_H[(size_t)(r + 8) * DBOT + col]) = v1;
                } else if (col < DBOT + NEXP) {
                    int c = col - DBOT;
                    *reinterpret_cast<float2*>(&g_L[(size_t)r * NEXP + c]) = v0;
                    *reinterpret_cast<float2*>(&g_L[(size_t)(r + 8) * NEXP + c]) = v1;
                }
            }
        }
    }
}

__global__ void __launch_bounds__(256, 2) k_gemm1() {
    gemm_body<1>(g_Xh, g_Xl, g_B1T_h, g_B1T_l, DMODEL,
                 blockIdx.x * 128, blockIdx.y * 128, nullptr, 0);
}
__global__ void __launch_bounds__(256, 2) k_gemm2(float* __restrict__ y) {
    gemm_body<0>(g_Zh, g_Zl, g_B2T_h, g_B2T_l, DBOT,
                 blockIdx.x * 128, blockIdx.y * 128, y, DMODEL);
}

// ================= routing (top-2 + softmax) =================
__global__ void k_route() {
    int nIdx = blockIdx.x * blockDim.x + threadIdx.x;
    if (nIdx >= NTOK) return;
    int b = nIdx >> 12;
    float mu = g_stats[b * 2 + 0];
    float rstd = g_stats[b * 2 + 1];
    float best = -1e30f, sec = -1e30f;
    int i0 = 0, i1 = 0;
#pragma unroll
    for (int e = 0; e < NEXP; e++) {
        float l = rstd * (g_L[nIdx * NEXP + e] - mu * g_cs[e]) + g_base[b * NEXP + e];
        if (l > best) { sec = best; i1 = i0; best = l; i0 = e; }
        else if (l > sec) { sec = l; i1 = e; }
    }
    float e1 = expf(sec - best);
    float inv = 1.f / (1.f + e1);
    g_sel[nIdx * 2 + 0] = i0;
    g_sel[nIdx * 2 + 1] = i1;
    g_w[nIdx * 2 + 0] = inv;
    g_w[nIdx * 2 + 1] = e1 * inv;
}

// ================= z = gelu(H) * combine, split to bf16 h/l =================
__global__ void k_z() {
    uint32_t* zh = reinterpret_cast<uint32_t*>(g_Zh);
    uint32_t* zl = reinterpret_cast<uint32_t*>(g_Zl);
    for (int i2 = blockIdx.x * blockDim.x + threadIdx.x; i2 < NTOK * DBOT / 2;
         i2 += gridDim.x * blockDim.x) {
        int idx = i2 * 2;
        int nn = idx >> 8;
        int j = idx & 255;
        float2 hv = *reinterpret_cast<const float2*>(&g_H[idx]);
        float w0 = g_w[nn * 2 + 0], w1 = g_w[nn * 2 + 1];
        const float* m0 = &g_gmask[g_sel[nn * 2 + 0] * DBOT + j];
        const float* m1 = &g_gmask[g_sel[nn * 2 + 1] * DBOT + j];
        float z[2];
#pragma unroll
        for (int t = 0; t < 2; t++) {
            float h = (t == 0) ? hv.x : hv.y;
            float inner = 0.7978845608028654f * (h + 0.044715f * h * h * h);
            float a = 0.5f * h * (1.f + tanhf(inner));
            z[t] = a * (w0 * m0[t] + w1 * m1[t]);
        }
        uint32_t h, l;
        split2(z[0], z[1], h, l);
        zh[i2] = h;
        zl[i2] = l;
    }
}

// ================= launch =================
extern "C" void kernel_launch(void* const* d_in, const int* in_sizes, int n_in,
                              void* d_out, int out_size) {
    const float* x        = (const float*)d_in[0];
    const int*   task_id  = (const int*)d_in[1];
    const float* task_emb = (const float*)d_in[2];
    const float* Wr       = (const float*)d_in[3];
    const float* br       = (const float*)d_in[4];
    const float* W_down   = (const float*)d_in[5];
    const float* W_up     = (const float*)d_in[6];
    const float* topo     = (const float*)d_in[7];
    float* y = (float*)d_out;

    cudaFuncSetAttribute(k_gemm1, cudaFuncAttributeMaxDynamicSharedMemorySize, 2 * BUFB);
    cudaFuncSetAttribute(k_gemm2, cudaFuncAttributeMaxDynamicSharedMemorySize, 2 * BUFB);

    k_stats<<<dim3(64, 2), 256>>>(x);
    k_setup<<<1, 256>>>(task_id, task_emb, Wr, br, topo);
    k_tsplit<<<dim3(8, 32),  dim3(32, 8)>>>(W_down, DMODEL, DBOT, 0);
    k_tsplit<<<dim3(1, 32),  dim3(32, 8)>>>(Wr,     DMODEL, NEXP, 1);
    k_tsplit<<<dim3(32, 8),  dim3(32, 8)>>>(W_up,   DBOT, DMODEL, 2);
    k_gemm1<<<dim3(3, 64), 256, 2 * BUFB>>>();
    k_route<<<32, 256>>>();
    k_z<<<1024, 256>>>();
    k_gemm2<<<dim3(8, 64), 256, 2 * BUFB>>>(y);
}

// round 6
// speedup vs baseline: 1.3231x; 1.3231x over previous
#include <cuda_runtime.h>
#include <cuda_bf16.h>
#include <math.h>
#include <stdint.h>

// Problem constants (fixed shapes from reference setup_inputs)
#define NTOK   8192      // B*S = 2*4096
#define SEQ    4096
#define DMODEL 1024
#define NEXP   16
#define DBOT   256
#define DTASK  32
#define RQUOTA 64

#define SA 40            // smem row stride in bf16 elems (80B, conflict-free)
#define BUFB 40960       // bytes per smem stage (4 arrays * 128*40*2)
#define OFF_AL 10240
#define OFF_BH 20480
#define OFF_BL 30720
#define NSTG 3
#define NPART 256        // stats partial blocks per batch

// ================= device scratch =================
__device__ float  g_H[NTOK * DBOT];
__device__ float  g_L[NTOK * NEXP];
__device__ float  g_gmask[NEXP * DBOT];
__device__ float  g_cs[NEXP];
__device__ float  g_base[2 * NEXP];
__device__ float  g_stats[4];
__device__ double g_part[2 * NPART * 2];
__device__ int    g_sel[NTOK * 2];
__device__ float  g_w[NTOK * 2];
// pre-split activations
__device__ __align__(16) __nv_bfloat16 g_Xh[NTOK * DMODEL];
__device__ __align__(16) __nv_bfloat16 g_Xl[NTOK * DMODEL];
__device__ __align__(16) __nv_bfloat16 g_Zh[NTOK * DBOT];
__device__ __align__(16) __nv_bfloat16 g_Zl[NTOK * DBOT];
// combined GEMM1 B: rows 0..255 = W_down^T, 256..271 = Wr[:D]^T, 272..383 zero
__device__ __align__(16) __nv_bfloat16 g_B1T_h[384 * DMODEL];
__device__ __align__(16) __nv_bfloat16 g_B1T_l[384 * DMODEL];
// GEMM2 B: W_up^T [1024][256]
__device__ __align__(16) __nv_bfloat16 g_B2T_h[DMODEL * DBOT];
__device__ __align__(16) __nv_bfloat16 g_B2T_l[DMODEL * DBOT];

// ================= helpers =================
__device__ __forceinline__ uint32_t smem_u32(const void* p) {
    uint32_t a;
    asm("{ .reg .u64 t; cvta.to.shared.u64 t, %1; cvt.u32.u64 %0, t; }" : "=r"(a) : "l"(p));
    return a;
}
__device__ __forceinline__ void cp16(uint32_t dst, const void* src) {
    asm volatile("cp.async.cg.shared.global [%0], [%1], 16;" :: "r"(dst), "l"(src));
}
#define CP_COMMIT() asm volatile("cp.async.commit_group;" ::: "memory")
#define CP_WAIT(n)  asm volatile("cp.async.wait_group %0;" :: "n"(n) : "memory")

#define LDSM4(d, addr) \
    asm volatile("ldmatrix.sync.aligned.m8n8.x4.shared.b16 {%0,%1,%2,%3}, [%4];" \
        : "=r"((d)[0]), "=r"((d)[1]), "=r"((d)[2]), "=r"((d)[3]) : "r"(addr))

__device__ __forceinline__ void mma16816(float* d, const uint32_t* a,
                                         const uint32_t* b) {
    asm volatile(
        "mma.sync.aligned.m16n8k16.row.col.f32.bf16.bf16.f32 "
        "{%0,%1,%2,%3}, {%4,%5,%6,%7}, {%8,%9}, {%0,%1,%2,%3};"
        : "+f"(d[0]), "+f"(d[1]), "+f"(d[2]), "+f"(d[3])
        : "r"(a[0]), "r"(a[1]), "r"(a[2]), "r"(a[3]), "r"(b[0]), "r"(b[1]));
}

__device__ __forceinline__ void split2(float x, float y, uint32_t& h, uint32_t& l) {
    __nv_bfloat162 hh = __float22bfloat162_rn(make_float2(x, y));
    float rx = x - __bfloat162float(hh.x);
    float ry = y - __bfloat162float(hh.y);
    __nv_bfloat162 ll = __float22bfloat162_rn(make_float2(rx, ry));
    h = *reinterpret_cast<uint32_t*>(&hh);
    l = *reinterpret_cast<uint32_t*>(&ll);
}

// ================= kernel 1: stats partials + x split =================
__global__ void k_stats(const float* __restrict__ x) {
    int b = blockIdx.y;
    const float4* xb = reinterpret_cast<const float4*>(x + (size_t)b * SEQ * DMODEL);
    uint2* xh = reinterpret_cast<uint2*>(g_Xh + (size_t)b * SEQ * DMODEL);
    uint2* xl = reinterpret_cast<uint2*>(g_Xl + (size_t)b * SEQ * DMODEL);
    const int nvec = SEQ * DMODEL / 4;
    double s = 0.0, q = 0.0;
    for (int i = blockIdx.x * blockDim.x + threadIdx.x; i < nvec;
         i += gridDim.x * blockDim.x) {
        float4 v = xb[i];
        s += (double)v.x; q += (double)v.x * v.x;
        s += (double)v.y; q += (double)v.y * v.y;
        s += (double)v.z; q += (double)v.z * v.z;
        s += (double)v.w; q += (double)v.w * v.w;
        uint32_t h0, l0, h1, l1;
        split2(v.x, v.y, h0, l0);
        split2(v.z, v.w, h1, l1);
        xh[i] = make_uint2(h0, h1);
        xl[i] = make_uint2(l0, l1);
    }
    __shared__ double rs[256], rq[256];
    rs[threadIdx.x] = s; rq[threadIdx.x] = q;
    __syncthreads();
    for (int st = 128; st > 0; st >>= 1) {
        if (threadIdx.x < st) {
            rs[threadIdx.x] += rs[threadIdx.x + st];
            rq[threadIdx.x] += rq[threadIdx.x + st];
        }
        __syncthreads();
    }
    if (threadIdx.x == 0) {
        g_part[(b * NPART + blockIdx.x) * 2 + 0] = rs[0];
        g_part[(b * NPART + blockIdx.x) * 2 + 1] = rq[0];
    }
}

// ================= kernel 2: block 0 = stats/router consts; blocks 1..16 = topo =================
__global__ void k_setup(const int* __restrict__ task_id,
                        const float* __restrict__ task_emb,
                        const float* __restrict__ Wr,
                        const float* __restrict__ br,
                        const float* __restrict__ topo) {
    int tid = threadIdx.x;
    if (blockIdx.x == 0) {
        __shared__ double rd[256];
        for (int b = 0; b < 2; b++) {
            double s = g_part[(b * NPART + tid) * 2 + 0];
            double q = g_part[(b * NPART + tid) * 2 + 1];
            rd[tid] = s; __syncthreads();
            for (int st = 128; st > 0; st >>= 1) {
                if (tid < st) rd[tid] += rd[tid + st];
                __syncthreads();
            }
            double S = rd[0]; __syncthreads();
            rd[tid] = q; __syncthreads();
            for (int st = 128; st > 0; st >>= 1) {
                if (tid < st) rd[tid] += rd[tid + st];
                __syncthreads();
            }
            double Q = rd[0]; __syncthreads();
            if (tid == 0) {
                const double cnt = (double)SEQ * DMODEL;
                double mu  = S / cnt;
                double var = Q / cnt - mu * mu;
                g_stats[b * 2 + 0] = (float)mu;
                g_stats[b * 2 + 1] = (float)(1.0 / sqrt(var + 1e-5));
            }
            __syncthreads();
        }
        {
            __shared__ float rf[256];
            int e = tid & 15, lane = tid >> 4;
            float p = 0.f;
            for (int d = lane; d < DMODEL; d += 16) p += Wr[d * NEXP + e];
            rf[tid] = p; __syncthreads();
            if (tid < 16) {
                float s2 = 0.f;
                for (int l = 0; l < 16; l++) s2 += rf[l * 16 + tid];
                g_cs[tid] = s2;
            }
            __syncthreads();
        }
        if (tid < 32) {
            int b = tid >> 4, e = tid & 15;
            int tI = task_id[b];
            float v = br[e];
            for (int t = 0; t < DTASK; t++)
                v += task_emb[tI * DTASK + t] * Wr[(DMODEL + t) * NEXP + e];
            g_base[b * NEXP + e] = v;
        }
    } else {
        // topo top-64 mask + gate for expert e (one block per expert)
        int e = blockIdx.x - 1;
        __shared__ float row[256];
        __shared__ float rs[256];
        row[tid] = topo[e * DBOT + tid];
        __syncthreads();
        float v = row[tid];
        int rank = 0;
#pragma unroll 16
        for (int i = 0; i < DBOT; i++) {
            float u = row[i];
            rank += (u > v) || (u == v && i < tid);
        }
        int sel = (rank < RQUOTA);
        rs[tid] = sel ? 1.f / (1.f + expf(-v)) : 0.f;
        __syncthreads();
        for (int st = 128; st > 0; st >>= 1) {
            if (tid < st) rs[tid] += rs[tid + st];
            __syncthreads();
        }
        float gate = rs[0] / (float)RQUOTA;
        g_gmask[e * DBOT + tid] = sel ? gate : 0.f;
    }
}

// ================= merged transpose + bf16-split of all weights (1 launch) =================
// blocks 0..255: W_down [1024,256] -> B1T rows [0,256)
// blocks 256..287: Wr[:1024] [.,16] -> B1T rows [256,272)
// blocks 288..543: W_up [256,1024] -> B2T
__global__ void k_tsplit(const float* __restrict__ W_down,
                         const float* __restrict__ Wr,
                         const float* __restrict__ W_up) {
    int bid = blockIdx.x;
    const float* in;
    __nv_bfloat16 *outh, *outl;
    int R, C, c0, r0;
    if (bid < 256) {
        in = W_down; outh = g_B1T_h; outl = g_B1T_l;
        R = DMODEL; C = DBOT;
        c0 = (bid & 7) * 32; r0 = (bid >> 3) * 32;
    } else if (bid < 288) {
        in = Wr; outh = g_B1T_h + 256 * DMODEL; outl = g_B1T_l + 256 * DMODEL;
        R = DMODEL; C = NEXP;
        c0 = 0; r0 = (bid - 256) * 32;
    } else {
        in = W_up; outh = g_B2T_h; outl = g_B2T_l;
        R = DBOT; C = DMODEL;
        int idx = bid - 288;
        c0 = (idx & 31) * 32; r0 = (idx >> 5) * 32;
    }

    __shared__ float t[32][33];
    int tx = threadIdx.x, ty = threadIdx.y;
#pragma unroll
    for (int i = 0; i < 32; i += 8) {
        int r = r0 + ty + i, c = c0 + tx;
        t[ty + i][tx] = (r < R && c < C) ? in[(size_t)r * C + c] : 0.f;
    }
    __syncthreads();
#pragma unroll
    for (int i = 0; i < 32; i += 8) {
        int c = c0 + ty + i, r = r0 + tx;
        if (c < C && r < R) {
            float v = t[tx][ty + i];
            __nv_bfloat16 h = __float2bfloat16(v);
            __nv_bfloat16 l = __float2bfloat16(v - __bfloat162float(h));
            outh[(size_t)c * R + r] = h;
            outl[(size_t)c * R + r] = l;
        }
    }
}

// ================= tensor GEMM core: cp.async 3-stage, 1 sync/chunk =================
// C[row0:+128, n0:+128] = A @ B^T (A [M][K] h/l, B [N][K] h/l)
// MODE 0: plain store (C, ldc). MODE 1: GEMM1 scatter (g_H <256, g_L 256..271)
template <int MODE>
__device__ __forceinline__ void gemm_body(
    const __nv_bfloat16* __restrict__ Ah, const __nv_bfloat16* __restrict__ Al,
    const __nv_bfloat16* __restrict__ Bh, const __nv_bfloat16* __restrict__ Bl,
    int K, int n0, int row0, float* __restrict__ C, int ldc)
{
    extern __shared__ char smem[];
    const int tid = threadIdx.x;
    const int wid = tid >> 5, lane = tid & 31;
    const int wm = wid >> 2, wn = wid & 3;    // 2x4 warp grid
    const bool active = (MODE == 0) || (n0 + wn * 32 < 272);

    float acc[4][4][4] = {};

    const int r4 = tid >> 2, j4 = tid & 3;    // cp.async fill: 64 rows/pass, 2 passes
    const uint32_t sb = smem_u32(smem);
    const uint32_t a_off = ((wm * 64 + (lane & 15)) * SA + (lane >> 4) * 8) * 2;
    const uint32_t b_off = ((wn * 32 + (lane >> 4) * 8 + (lane & 7)) * SA
                            + ((lane >> 3) & 1) * 8) * 2;
    const int nch = K >> 5;

#define ISSUE(ch) do { \
    const uint32_t _db = sb + ((ch) % NSTG) * BUFB; \
    const int _k0 = (ch) * 32; \
    _Pragma("unroll") \
    for (int p = 0; p < 2; p++) { \
        uint32_t d = _db + ((p * 64 + r4) * 5 + j4) * 16; \
        size_t ai = (size_t)(row0 + p * 64 + r4) * K + _k0 + j4 * 8; \
        cp16(d, Ah + ai); \
        cp16(d + OFF_AL, Al + ai); \
        size_t bi = (size_t)(n0 + p * 64 + r4) * K + _k0 + j4 * 8; \
        cp16(d + OFF_BH, Bh + bi); \
        cp16(d + OFF_BL, Bl + bi); \
    } \
    CP_COMMIT(); } while (0)

    ISSUE(0);
    ISSUE(1);   // nch >= 8 always

    for (int ch = 0; ch < nch; ch++) {
        if (ch + 1 < nch) { CP_WAIT(1); } else { CP_WAIT(0); }
        __syncthreads();   // all warps done with MMA(ch-1) AND chunk ch data landed
        // issue into stage (ch+2)%3 == (ch-1)%3, protected by the barrier above
        if (ch + 2 < nch) ISSUE(ch + 2);

        if (active) {
            const uint32_t ab = sb + (ch % NSTG) * BUFB;
#pragma unroll
            for (int ks = 0; ks < 2; ks++) {
                const uint32_t koff = ks * 32;  // 16 elems * 2B
                uint32_t ah[4][4], bb[4][2];
#pragma unroll
                for (int mt = 0; mt < 4; mt++)
                    LDSM4(ah[mt], ab + a_off + mt * (16 * SA * 2) + koff);
#pragma unroll
                for (int p = 0; p < 2; p++)
                    LDSM4(&bb[2 * p][0], ab + OFF_BH + b_off + p * (16 * SA * 2) + koff);
                // Ah * Bh
#pragma unroll
                for (int mt = 0; mt < 4; mt++)
#pragma unroll
                    for (int nt = 0; nt < 4; nt++)
                        mma16816(acc[mt][nt], ah[mt], bb[nt]);
                // Al * Bh (reload Al one m-tile at a time)
#pragma unroll
                for (int mt = 0; mt < 4; mt++) {
                    uint32_t al4[4];
                    LDSM4(al4, ab + OFF_AL + a_off + mt * (16 * SA * 2) + koff);
#pragma unroll
                    for (int nt = 0; nt < 4; nt++)
                        mma16816(acc[mt][nt], al4, bb[nt]);
                }
                // Ah * Bl
#pragma unroll
                for (int p = 0; p < 2; p++)
                    LDSM4(&bb[2 * p][0], ab + OFF_BL + b_off + p * (16 * SA * 2) + koff);
#pragma unroll
                for (int mt = 0; mt < 4; mt++)
#pragma unroll
                    for (int nt = 0; nt < 4; nt++)
                        mma16816(acc[mt][nt], ah[mt], bb[nt]);
            }
        }
    }
#undef ISSUE

    if (!active) return;
    const int g = lane >> 2, tig = lane & 3;
#pragma unroll
    for (int mt = 0; mt < 4; mt++) {
        int r = row0 + wm * 64 + mt * 16 + g;
#pragma unroll
        for (int nt = 0; nt < 4; nt++) {
            int col = n0 + wn * 32 + nt * 8 + 2 * tig;
            float2 v0 = make_float2(acc[mt][nt][0], acc[mt][nt][1]);
            float2 v1 = make_float2(acc[mt][nt][2], acc[mt][nt][3]);
            if (MODE == 0) {
                *reinterpret_cast<float2*>(&C[(size_t)r * ldc + col]) = v0;
                *reinterpret_cast<float2*>(&C[(size_t)(r + 8) * ldc + col]) = v1;
            } else {
                if (col < DBOT) {
                    *reinterpret_cast<float2*>(&g_H[(size_t)r * DBOT + col]) = v0;
                    *reinterpret_cast<float2*>(&g_H[(size_t)(r + 8) * DBOT + col]) = v1;
                } else if (col < DBOT + NEXP) {
                    int c = col - DBOT;
                    *reinterpret_cast<float2*>(&g_L[(size_t)r * NEXP + c]) = v0;
                    *reinterpret_cast<float2*>(&g_L[(size_t)(r + 8) * NEXP + c]) = v1;
                }
            }
        }
    }
}

__global__ void __launch_bounds__(256) k_gemm1() {
    gemm_body<1>(g_Xh, g_Xl, g_B1T_h, g_B1T_l, DMODEL,
                 blockIdx.x * 128, blockIdx.y * 128, nullptr, 0);
}
__global__ void __launch_bounds__(256) k_gemm2(float* __restrict__ y) {
    gemm_body<0>(g_Zh, g_Zl, g_B2T_h, g_B2T_l, DBOT,
                 blockIdx.x * 128, blockIdx.y * 128, y, DMODEL);
}

// ================= routing (top-2 + softmax) =================
__global__ void k_route() {
    int nIdx = blockIdx.x * blockDim.x + threadIdx.x;
    if (nIdx >= NTOK) return;
    int b = nIdx >> 12;
    float mu = g_stats[b * 2 + 0];
    float rstd = g_stats[b * 2 + 1];
    float best = -1e30f, sec = -1e30f;
    int i0 = 0, i1 = 0;
#pragma unroll
    for (int e = 0; e < NEXP; e++) {
        float l = rstd * (g_L[nIdx * NEXP + e] - mu * g_cs[e]) + g_base[b * NEXP + e];
        if (l > best) { sec = best; i1 = i0; best = l; i0 = e; }
        else if (l > sec) { sec = l; i1 = e; }
    }
    float e1 = expf(sec - best);
    float inv = 1.f / (1.f + e1);
    g_sel[nIdx * 2 + 0] = i0;
    g_sel[nIdx * 2 + 1] = i1;
    g_w[nIdx * 2 + 0] = inv;
    g_w[nIdx * 2 + 1] = e1 * inv;
}

// ================= z = gelu(H) * combine, split to bf16 h/l =================
__global__ void k_z() {
    uint32_t* zh = reinterpret_cast<uint32_t*>(g_Zh);
    uint32_t* zl = reinterpret_cast<uint32_t*>(g_Zl);
    for (int i2 = blockIdx.x * blockDim.x + threadIdx.x; i2 < NTOK * DBOT / 2;
         i2 += gridDim.x * blockDim.x) {
        int idx = i2 * 2;
        int nn = idx >> 8;
        int j = idx & 255;
        float2 hv = *reinterpret_cast<const float2*>(&g_H[idx]);
        float w0 = g_w[nn * 2 + 0], w1 = g_w[nn * 2 + 1];
        const float* m0 = &g_gmask[g_sel[nn * 2 + 0] * DBOT + j];
        const float* m1 = &g_gmask[g_sel[nn * 2 + 1] * DBOT + j];
        float z[2];
#pragma unroll
        for (int t = 0; t < 2; t++) {
            float h = (t == 0) ? hv.x : hv.y;
            float inner = 0.7978845608028654f * (h + 0.044715f * h * h * h);
            float a = 0.5f * h * (1.f + tanhf(inner));
            z[t] = a * (w0 * m0[t] + w1 * m1[t]);
        }
        uint32_t h, l;
        split2(z[0], z[1], h, l);
        zh[i2] = h;
        zl[i2] = l;
    }
}

// ================= launch =================
extern "C" void kernel_launch(void* const* d_in, const int* in_sizes, int n_in,
                              void* d_out, int out_size) {
    const float* x        = (const float*)d_in[0];
    const int*   task_id  = (const int*)d_in[1];
    const float* task_emb = (const float*)d_in[2];
    const float* Wr       = (const float*)d_in[3];
    const float* br       = (const float*)d_in[4];
    const float* W_down   = (const float*)d_in[5];
    const float* W_up     = (const float*)d_in[6];
    const float* topo     = (const float*)d_in[7];
    float* y = (float*)d_out;

    cudaFuncSetAttribute(k_gemm1, cudaFuncAttributeMaxDynamicSharedMemorySize, NSTG * BUFB);
    cudaFuncSetAttribute(k_gemm2, cudaFuncAttributeMaxDynamicSharedMemorySize, NSTG * BUFB);

    k_stats<<<dim3(NPART, 2), 256>>>(x);
    k_setup<<<17, 256>>>(task_id, task_emb, Wr, br, topo);
    k_tsplit<<<544, dim3(32, 8)>>>(W_down, Wr, W_up);
    k_gemm1<<<dim3(3, 64), 256, NSTG * BUFB>>>();   // launch #4 -> profiled
    k_route<<<32, 256>>>();
    k_z<<<1024, 256>>>();
    k_gemm2<<<dim3(8, 64), 256, NSTG * BUFB>>>(y);
}

// round 7
// speedup vs baseline: 1.6457x; 1.2438x over previous
#include <cuda_runtime.h>
#include <cuda_bf16.h>
#include <math.h>
#include <stdint.h>

// Problem constants (fixed shapes from reference setup_inputs)
#define NTOK   8192      // B*S = 2*4096
#define SEQ    4096
#define DMODEL 1024
#define NEXP   16
#define DBOT   256
#define DTASK  32
#define RQUOTA 64

// swizzled smem layout: 128 rows x 64B (32 bf16) per array, 16B-chunk XOR swizzle
#define BUFB   32768     // bytes per stage (4 arrays * 8KB)
#define OFF_AL 8192
#define OFF_BH 16384
#define OFF_BL 24576
#define NSTG 3
#define NPART 256        // stats partial blocks per batch

// ================= device scratch =================
__device__ float  g_H[NTOK * DBOT];
__device__ float  g_L[NTOK * NEXP];
__device__ float  g_gmask[NEXP * DBOT];
__device__ float  g_cs[NEXP];
__device__ float  g_base[2 * NEXP];
__device__ float  g_stats[4];
__device__ double g_part[2 * NPART * 2];
__device__ int    g_sel[NTOK * 2];
__device__ float  g_w[NTOK * 2];
// pre-split activations
__device__ __align__(16) __nv_bfloat16 g_Xh[NTOK * DMODEL];
__device__ __align__(16) __nv_bfloat16 g_Xl[NTOK * DMODEL];
__device__ __align__(16) __nv_bfloat16 g_Zh[NTOK * DBOT];
__device__ __align__(16) __nv_bfloat16 g_Zl[NTOK * DBOT];
// combined GEMM1 B: rows 0..255 = W_down^T, 256..271 = Wr[:D]^T, 272..383 zero
__device__ __align__(16) __nv_bfloat16 g_B1T_h[384 * DMODEL];
__device__ __align__(16) __nv_bfloat16 g_B1T_l[384 * DMODEL];
// GEMM2 B: W_up^T [1024][256]
__device__ __align__(16) __nv_bfloat16 g_B2T_h[DMODEL * DBOT];
__device__ __align__(16) __nv_bfloat16 g_B2T_l[DMODEL * DBOT];

// ================= helpers =================
__device__ __forceinline__ uint32_t smem_u32(const void* p) {
    uint32_t a;
    asm("{ .reg .u64 t; cvta.to.shared.u64 t, %1; cvt.u32.u64 %0, t; }" : "=r"(a) : "l"(p));
    return a;
}
__device__ __forceinline__ void cp16(uint32_t dst, const void* src) {
    asm volatile("cp.async.cg.shared.global [%0], [%1], 16;" :: "r"(dst), "l"(src));
}
#define CP_COMMIT() asm volatile("cp.async.commit_group;" ::: "memory")
#define CP_WAIT(n)  asm volatile("cp.async.wait_group %0;" :: "n"(n) : "memory")

#define LDSM4(d, addr) \
    asm volatile("ldmatrix.sync.aligned.m8n8.x4.shared.b16 {%0,%1,%2,%3}, [%4];" \
        : "=r"((d)[0]), "=r"((d)[1]), "=r"((d)[2]), "=r"((d)[3]) : "r"(addr))

__device__ __forceinline__ void mma16816(float* d, const uint32_t* a,
                                         const uint32_t* b) {
    asm volatile(
        "mma.sync.aligned.m16n8k16.row.col.f32.bf16.bf16.f32 "
        "{%0,%1,%2,%3}, {%4,%5,%6,%7}, {%8,%9}, {%0,%1,%2,%3};"
        : "+f"(d[0]), "+f"(d[1]), "+f"(d[2]), "+f"(d[3])
        : "r"(a[0]), "r"(a[1]), "r"(a[2]), "r"(a[3]), "r"(b[0]), "r"(b[1]));
}

__device__ __forceinline__ void split2(float x, float y, uint32_t& h, uint32_t& l) {
    __nv_bfloat162 hh = __float22bfloat162_rn(make_float2(x, y));
    float rx = x - __bfloat162float(hh.x);
    float ry = y - __bfloat162float(hh.y);
    __nv_bfloat162 ll = __float22bfloat162_rn(make_float2(rx, ry));
    h = *reinterpret_cast<uint32_t*>(&hh);
    l = *reinterpret_cast<uint32_t*>(&ll);
}

// ================= kernel 1: stats partials + x split =================
__global__ void k_stats(const float* __restrict__ x) {
    int b = blockIdx.y;
    const float4* xb = reinterpret_cast<const float4*>(x + (size_t)b * SEQ * DMODEL);
    uint2* xh = reinterpret_cast<uint2*>(g_Xh + (size_t)b * SEQ * DMODEL);
    uint2* xl = reinterpret_cast<uint2*>(g_Xl + (size_t)b * SEQ * DMODEL);
    const int nvec = SEQ * DMODEL / 4;
    double s = 0.0, q = 0.0;
    for (int i = blockIdx.x * blockDim.x + threadIdx.x; i < nvec;
         i += gridDim.x * blockDim.x) {
        float4 v = xb[i];
        s += (double)v.x; q += (double)v.x * v.x;
        s += (double)v.y; q += (double)v.y * v.y;
        s += (double)v.z; q += (double)v.z * v.z;
        s += (double)v.w; q += (double)v.w * v.w;
        uint32_t h0, l0, h1, l1;
        split2(v.x, v.y, h0, l0);
        split2(v.z, v.w, h1, l1);
        xh[i] = make_uint2(h0, h1);
        xl[i] = make_uint2(l0, l1);
    }
    __shared__ double rs[256], rq[256];
    rs[threadIdx.x] = s; rq[threadIdx.x] = q;
    __syncthreads();
    for (int st = 128; st > 0; st >>= 1) {
        if (threadIdx.x < st) {
            rs[threadIdx.x] += rs[threadIdx.x + st];
            rq[threadIdx.x] += rq[threadIdx.x + st];
        }
        __syncthreads();
    }
    if (threadIdx.x == 0) {
        g_part[(b * NPART + blockIdx.x) * 2 + 0] = rs[0];
        g_part[(b * NPART + blockIdx.x) * 2 + 1] = rq[0];
    }
}

// ================= kernel 2: block 0 = stats/router consts; blocks 1..16 = topo =================
__global__ void k_setup(const int* __restrict__ task_id,
                        const float* __restrict__ task_emb,
                        const float* __restrict__ Wr,
                        const float* __restrict__ br,
                        const float* __restrict__ topo) {
    int tid = threadIdx.x;
    if (blockIdx.x == 0) {
        __shared__ double rd[256];
        for (int b = 0; b < 2; b++) {
            double s = g_part[(b * NPART + tid) * 2 + 0];
            double q = g_part[(b * NPART + tid) * 2 + 1];
            rd[tid] = s; __syncthreads();
            for (int st = 128; st > 0; st >>= 1) {
                if (tid < st) rd[tid] += rd[tid + st];
                __syncthreads();
            }
            double S = rd[0]; __syncthreads();
            rd[tid] = q; __syncthreads();
            for (int st = 128; st > 0; st >>= 1) {
                if (tid < st) rd[tid] += rd[tid + st];
                __syncthreads();
            }
            double Q = rd[0]; __syncthreads();
            if (tid == 0) {
                const double cnt = (double)SEQ * DMODEL;
                double mu  = S / cnt;
                double var = Q / cnt - mu * mu;
                g_stats[b * 2 + 0] = (float)mu;
                g_stats[b * 2 + 1] = (float)(1.0 / sqrt(var + 1e-5));
            }
            __syncthreads();
        }
        {
            __shared__ float rf[256];
            int e = tid & 15, lane = tid >> 4;
            float p = 0.f;
            for (int d = lane; d < DMODEL; d += 16) p += Wr[d * NEXP + e];
            rf[tid] = p; __syncthreads();
            if (tid < 16) {
                float s2 = 0.f;
                for (int l = 0; l < 16; l++) s2 += rf[l * 16 + tid];
                g_cs[tid] = s2;
            }
            __syncthreads();
        }
        if (tid < 32) {
            int b = tid >> 4, e = tid & 15;
            int tI = task_id[b];
            float v = br[e];
            for (int t = 0; t < DTASK; t++)
                v += task_emb[tI * DTASK + t] * Wr[(DMODEL + t) * NEXP + e];
            g_base[b * NEXP + e] = v;
        }
    } else {
        int e = blockIdx.x - 1;
        __shared__ float row[256];
        __shared__ float rs[256];
        row[tid] = topo[e * DBOT + tid];
        __syncthreads();
        float v = row[tid];
        int rank = 0;
#pragma unroll 16
        for (int i = 0; i < DBOT; i++) {
            float u = row[i];
            rank += (u > v) || (u == v && i < tid);
        }
        int sel = (rank < RQUOTA);
        rs[tid] = sel ? 1.f / (1.f + expf(-v)) : 0.f;
        __syncthreads();
        for (int st = 128; st > 0; st >>= 1) {
            if (tid < st) rs[tid] += rs[tid + st];
            __syncthreads();
        }
        float gate = rs[0] / (float)RQUOTA;
        g_gmask[e * DBOT + tid] = sel ? gate : 0.f;
    }
}

// ================= merged transpose + bf16-split of all weights =================
__global__ void k_tsplit(const float* __restrict__ W_down,
                         const float* __restrict__ Wr,
                         const float* __restrict__ W_up) {
    int bid = blockIdx.x;
    const float* in;
    __nv_bfloat16 *outh, *outl;
    int R, C, c0, r0;
    if (bid < 256) {
        in = W_down; outh = g_B1T_h; outl = g_B1T_l;
        R = DMODEL; C = DBOT;
        c0 = (bid & 7) * 32; r0 = (bid >> 3) * 32;
    } else if (bid < 288) {
        in = Wr; outh = g_B1T_h + 256 * DMODEL; outl = g_B1T_l + 256 * DMODEL;
        R = DMODEL; C = NEXP;
        c0 = 0; r0 = (bid - 256) * 32;
    } else {
        in = W_up; outh = g_B2T_h; outl = g_B2T_l;
        R = DBOT; C = DMODEL;
        int idx = bid - 288;
        c0 = (idx & 31) * 32; r0 = (idx >> 5) * 32;
    }

    __shared__ float t[32][33];
    int tx = threadIdx.x, ty = threadIdx.y;
#pragma unroll
    for (int i = 0; i < 32; i += 8) {
        int r = r0 + ty + i, c = c0 + tx;
        t[ty + i][tx] = (r < R && c < C) ? in[(size_t)r * C + c] : 0.f;
    }
    __syncthreads();
#pragma unroll
    for (int i = 0; i < 32; i += 8) {
        int c = c0 + ty + i, r = r0 + tx;
        if (c < C && r < R) {
            float v = t[tx][ty + i];
            __nv_bfloat16 h = __float2bfloat16(v);
            __nv_bfloat16 l = __float2bfloat16(v - __bfloat162float(h));
            outh[(size_t)c * R + r] = h;
            outl[(size_t)c * R + r] = l;
        }
    }
}

// ================= tensor GEMM core: swizzled smem, cp.async 3-stage, 1 sync/chunk =================
// C[row0:+128, n0:+128] = A @ B^T (A [M][K] h/l, B [N][K] h/l)
// smem array layout: row r (0..127) x 4 chunks of 16B; phys chunk = c ^ ((r>>1)&3)
// MODE 0: plain store (C, ldc). MODE 1: GEMM1 scatter (g_H <256, g_L 256..271)
template <int MODE>
__device__ __forceinline__ void gemm_body(
    const __nv_bfloat16* __restrict__ Ah, const __nv_bfloat16* __restrict__ Al,
    const __nv_bfloat16* __restrict__ Bh, const __nv_bfloat16* __restrict__ Bl,
    int K, int n0, int row0, float* __restrict__ C, int ldc)
{
    extern __shared__ char smem[];
    const int tid = threadIdx.x;
    const int wid = tid >> 5, lane = tid & 31;
    const int wm = wid >> 2, wn = wid & 3;    // 2x4 warp grid
    const bool active = (MODE == 0) || (n0 + wn * 32 < 272);

    float acc[4][4][4] = {};

    // cp.async fill coords: 64 rows/pass (2 passes), 4 chunks/row
    const int r4 = tid >> 2, j4 = tid & 3;
    const int v4 = (r4 >> 1) & 3;             // row-swizzle (pass-invariant)
    const uint32_t fill_off = (uint32_t)(r4 * 64 + (j4 ^ v4) * 16);
    const uint32_t sb = smem_u32(smem);

    // ldmatrix logical coords
    const int ra = wm * 64 + (lane & 15);            // A row (+ mt*16)
    const int ca = lane >> 4;                        // A 16B chunk (+ ks*2)
    const int va = (ra >> 1) & 3;                    // mt*16 shift ≡ 0 mod 4
    const int rb = wn * 32 + ((lane >> 4) << 3) + (lane & 7);  // B row (+ p*16)
    const int cb = (lane >> 3) & 1;                  // B chunk (+ ks*2)
    const int vb = (rb >> 1) & 3;
    const uint32_t a_base = (uint32_t)(ra * 64);
    const uint32_t b_base = (uint32_t)(rb * 64);

    const int nch = K >> 5;

#define ISSUE(ch) do { \
    const uint32_t _db = sb + ((ch) % NSTG) * BUFB; \
    const int _k0 = (ch) * 32; \
    _Pragma("unroll") \
    for (int p = 0; p < 2; p++) { \
        uint32_t d = _db + (uint32_t)(p * 4096) + fill_off; \
        size_t ai = (size_t)(row0 + p * 64 + r4) * K + _k0 + j4 * 8; \
        cp16(d, Ah + ai); \
        cp16(d + OFF_AL, Al + ai); \
        size_t bi = (size_t)(n0 + p * 64 + r4) * K + _k0 + j4 * 8; \
        cp16(d + OFF_BH, Bh + bi); \
        cp16(d + OFF_BL, Bl + bi); \
    } \
    CP_COMMIT(); } while (0)

    ISSUE(0);
    ISSUE(1);   // nch >= 8 always

    for (int ch = 0; ch < nch; ch++) {
        if (ch + 1 < nch) { CP_WAIT(1); } else { CP_WAIT(0); }
        __syncthreads();   // MMA(ch-1) done everywhere AND chunk ch landed
        if (ch + 2 < nch) ISSUE(ch + 2);   // stage (ch+2)%3 == (ch-1)%3, safe

        if (active) {
            const uint32_t ab = sb + (ch % NSTG) * BUFB;
#pragma unroll
            for (int ks = 0; ks < 2; ks++) {
                const uint32_t aoff = ab + a_base + (uint32_t)(((ca + 2 * ks) ^ va) * 16);
                const uint32_t boff = ab + OFF_BH + b_base
                                    + (uint32_t)(((cb + 2 * ks) ^ vb) * 16);
                uint32_t ah[4][4], bb[4][2];
#pragma unroll
                for (int mt = 0; mt < 4; mt++)
                    LDSM4(ah[mt], aoff + mt * 1024);
#pragma unroll
                for (int p = 0; p < 2; p++)
                    LDSM4(&bb[2 * p][0], boff + p * 1024);
                // Ah * Bh
#pragma unroll
                for (int mt = 0; mt < 4; mt++)
#pragma unroll
                    for (int nt = 0; nt < 4; nt++)
                        mma16816(acc[mt][nt], ah[mt], bb[nt]);
                // Al * Bh (reload Al one m-tile at a time)
#pragma unroll
                for (int mt = 0; mt < 4; mt++) {
                    uint32_t al4[4];
                    LDSM4(al4, aoff + OFF_AL + mt * 1024);
#pragma unroll
                    for (int nt = 0; nt < 4; nt++)
                        mma16816(acc[mt][nt], al4, bb[nt]);
                }
                // Ah * Bl
#pragma unroll
                for (int p = 0; p < 2; p++)
                    LDSM4(&bb[2 * p][0], boff + OFF_AL + p * 1024); // OFF_BL = OFF_BH + OFF_AL
#pragma unroll
                for (int mt = 0; mt < 4; mt++)
#pragma unroll
                    for (int nt = 0; nt < 4; nt++)
                        mma16816(acc[mt][nt], ah[mt], bb[nt]);
            }
        }
    }
#undef ISSUE

    if (!active) return;
    const int g = lane >> 2, tig = lane & 3;
#pragma unroll
    for (int mt = 0; mt < 4; mt++) {
        int r = row0 + wm * 64 + mt * 16 + g;
#pragma unroll
        for (int nt = 0; nt < 4; nt++) {
            int col = n0 + wn * 32 + nt * 8 + 2 * tig;
            float2 v0 = make_float2(acc[mt][nt][0], acc[mt][nt][1]);
            float2 v1 = make_float2(acc[mt][nt][2], acc[mt][nt][3]);
            if (MODE == 0) {
                *reinterpret_cast<float2*>(&C[(size_t)r * ldc + col]) = v0;
                *reinterpret_cast<float2*>(&C[(size_t)(r + 8) * ldc + col]) = v1;
            } else {
                if (col < DBOT) {
                    *reinterpret_cast<float2*>(&g_H[(size_t)r * DBOT + col]) = v0;
                    *reinterpret_cast<float2*>(&g_H[(size_t)(r + 8) * DBOT + col]) = v1;
                } else if (col < DBOT + NEXP) {
                    int c = col - DBOT;
                    *reinterpret_cast<float2*>(&g_L[(size_t)r * NEXP + c]) = v0;
                    *reinterpret_cast<float2*>(&g_L[(size_t)(r + 8) * NEXP + c]) = v1;
                }
            }
        }
    }
}

__global__ void __launch_bounds__(256, 2) k_gemm1() {
    gemm_body<1>(g_Xh, g_Xl, g_B1T_h, g_B1T_l, DMODEL,
                 blockIdx.x * 128, blockIdx.y * 128, nullptr, 0);
}
__global__ void __launch_bounds__(256, 2) k_gemm2(float* __restrict__ y) {
    gemm_body<0>(g_Zh, g_Zl, g_B2T_h, g_B2T_l, DBOT,
                 blockIdx.x * 128, blockIdx.y * 128, y, DMODEL);
}

// ================= routing (top-2 + softmax) =================
__global__ void k_route() {
    int nIdx = blockIdx.x * blockDim.x + threadIdx.x;
    if (nIdx >= NTOK) return;
    int b = nIdx >> 12;
    float mu = g_stats[b * 2 + 0];
    float rstd = g_stats[b * 2 + 1];
    float best = -1e30f, sec = -1e30f;
    int i0 = 0, i1 = 0;
#pragma unroll
    for (int e = 0; e < NEXP; e++) {
        float l = rstd * (g_L[nIdx * NEXP + e] - mu * g_cs[e]) + g_base[b * NEXP + e];
        if (l > best) { sec = best; i1 = i0; best = l; i0 = e; }
        else if (l > sec) { sec = l; i1 = e; }
    }
    float e1 = expf(sec - best);
    float inv = 1.f / (1.f + e1);
    g_sel[nIdx * 2 + 0] = i0;
    g_sel[nIdx * 2 + 1] = i1;
    g_w[nIdx * 2 + 0] = inv;
    g_w[nIdx * 2 + 1] = e1 * inv;
}

// ================= z = gelu(H) * combine, split to bf16 h/l =================
__global__ void k_z() {
    uint32_t* zh = reinterpret_cast<uint32_t*>(g_Zh);
    uint32_t* zl = reinterpret_cast<uint32_t*>(g_Zl);
    for (int i2 = blockIdx.x * blockDim.x + threadIdx.x; i2 < NTOK * DBOT / 2;
         i2 += gridDim.x * blockDim.x) {
        int idx = i2 * 2;
        int nn = idx >> 8;
        int j = idx & 255;
        float2 hv = *reinterpret_cast<const float2*>(&g_H[idx]);
        float w0 = g_w[nn * 2 + 0], w1 = g_w[nn * 2 + 1];
        const float* m0 = &g_gmask[g_sel[nn * 2 + 0] * DBOT + j];
        const float* m1 = &g_gmask[g_sel[nn * 2 + 1] * DBOT + j];
        float z[2];
#pragma unroll
        for (int t = 0; t < 2; t++) {
            float h = (t == 0) ? hv.x : hv.y;
            float inner = 0.7978845608028654f * (h + 0.044715f * h * h * h);
            float a = 0.5f * h * (1.f + tanhf(inner));
            z[t] = a * (w0 * m0[t] + w1 * m1[t]);
        }
        uint32_t h, l;
        split2(z[0], z[1], h, l);
        zh[i2] = h;
        zl[i2] = l;
    }
}

// ================= launch =================
extern "C" void kernel_launch(void* const* d_in, const int* in_sizes, int n_in,
                              void* d_out, int out_size) {
    const float* x        = (const float*)d_in[0];
    const int*   task_id  = (const int*)d_in[1];
    const float* task_emb = (const float*)d_in[2];
    const float* Wr       = (const float*)d_in[3];
    const float* br       = (const float*)d_in[4];
    const float* W_down   = (const float*)d_in[5];
    const float* W_up     = (const float*)d_in[6];
    const float* topo     = (const float*)d_in[7];
    float* y = (float*)d_out;

    cudaFuncSetAttribute(k_gemm1, cudaFuncAttributeMaxDynamicSharedMemorySize, NSTG * BUFB);
    cudaFuncSetAttribute(k_gemm2, cudaFuncAttributeMaxDynamicSharedMemorySize, NSTG * BUFB);

    k_stats<<<dim3(NPART, 2), 256>>>(x);
    k_setup<<<17, 256>>>(task_id, task_emb, Wr, br, topo);
    k_tsplit<<<544, dim3(32, 8)>>>(W_down, Wr, W_up);
    k_gemm1<<<dim3(3, 64), 256, NSTG * BUFB>>>();   // launch #4 -> profiled
    k_route<<<32, 256>>>();
    k_z<<<1024, 256>>>();
    k_gemm2<<<dim3(8, 64), 256, NSTG * BUFB>>>(y);
}

// round 8
// speedup vs baseline: 1.8676x; 1.1349x over previous
#include <cuda_runtime.h>
#include <cuda_bf16.h>
#include <math.h>
#include <stdint.h>

// Problem constants (fixed shapes from reference setup_inputs)
#define NTOK   8192      // B*S = 2*4096
#define SEQ    4096
#define DMODEL 1024
#define NEXP   16
#define DBOT   256
#define DTASK  32
#define RQUOTA 64

// CTA tile 64x128, swizzled smem: A 64 rows, B 128 rows, 64B/row, 16B-chunk XOR swizzle
#define BUFB   24576     // bytes per stage: Ah 4K | Al 4K | Bh 8K | Bl 8K
#define OFF_AL 4096
#define OFF_BH 8192
#define OFF_BD 8192      // Bl = Bh + 8192
#define NSTG 2
#define NPART 256        // stats partial blocks per batch

// ================= device scratch =================
__device__ float  g_H[NTOK * DBOT];
__device__ float  g_L[NTOK * NEXP];
__device__ float  g_gmask[NEXP * DBOT];
__device__ float  g_cs[NEXP];
__device__ float  g_base[2 * NEXP];
__device__ float  g_stats[4];
__device__ double g_part[2 * NPART * 2];
__device__ int    g_sel[NTOK * 2];
__device__ float  g_w[NTOK * 2];
// pre-split activations
__device__ __align__(16) __nv_bfloat16 g_Xh[NTOK * DMODEL];
__device__ __align__(16) __nv_bfloat16 g_Xl[NTOK * DMODEL];
__device__ __align__(16) __nv_bfloat16 g_Zh[NTOK * DBOT];
__device__ __align__(16) __nv_bfloat16 g_Zl[NTOK * DBOT];
// combined GEMM1 B: rows 0..255 = W_down^T, 256..271 = Wr[:D]^T, 272..383 zero
__device__ __align__(16) __nv_bfloat16 g_B1T_h[384 * DMODEL];
__device__ __align__(16) __nv_bfloat16 g_B1T_l[384 * DMODEL];
// GEMM2 B: W_up^T [1024][256]
__device__ __align__(16) __nv_bfloat16 g_B2T_h[DMODEL * DBOT];
__device__ __align__(16) __nv_bfloat16 g_B2T_l[DMODEL * DBOT];

// ================= helpers =================
__device__ __forceinline__ uint32_t smem_u32(const void* p) {
    uint32_t a;
    asm("{ .reg .u64 t; cvta.to.shared.u64 t, %1; cvt.u32.u64 %0, t; }" : "=r"(a) : "l"(p));
    return a;
}
__device__ __forceinline__ void cp16(uint32_t dst, const void* src) {
    asm volatile("cp.async.cg.shared.global [%0], [%1], 16;" :: "r"(dst), "l"(src));
}
#define CP_COMMIT() asm volatile("cp.async.commit_group;" ::: "memory")
#define CP_WAIT(n)  asm volatile("cp.async.wait_group %0;" :: "n"(n) : "memory")

#define LDSM4(d, addr) \
    asm volatile("ldmatrix.sync.aligned.m8n8.x4.shared.b16 {%0,%1,%2,%3}, [%4];" \
        : "=r"((d)[0]), "=r"((d)[1]), "=r"((d)[2]), "=r"((d)[3]) : "r"(addr))

__device__ __forceinline__ void mma16816(float* d, const uint32_t* a,
                                         const uint32_t* b) {
    asm volatile(
        "mma.sync.aligned.m16n8k16.row.col.f32.bf16.bf16.f32 "
        "{%0,%1,%2,%3}, {%4,%5,%6,%7}, {%8,%9}, {%0,%1,%2,%3};"
        : "+f"(d[0]), "+f"(d[1]), "+f"(d[2]), "+f"(d[3])
        : "r"(a[0]), "r"(a[1]), "r"(a[2]), "r"(a[3]), "r"(b[0]), "r"(b[1]));
}

__device__ __forceinline__ void split2(float x, float y, uint32_t& h, uint32_t& l) {
    __nv_bfloat162 hh = __float22bfloat162_rn(make_float2(x, y));
    float rx = x - __bfloat162float(hh.x);
    float ry = y - __bfloat162float(hh.y);
    __nv_bfloat162 ll = __float22bfloat162_rn(make_float2(rx, ry));
    h = *reinterpret_cast<uint32_t*>(&hh);
    l = *reinterpret_cast<uint32_t*>(&ll);
}

// ================= kernel 1: stats partials + x split =================
__global__ void k_stats(const float* __restrict__ x) {
    int b = blockIdx.y;
    const float4* xb = reinterpret_cast<const float4*>(x + (size_t)b * SEQ * DMODEL);
    uint2* xh = reinterpret_cast<uint2*>(g_Xh + (size_t)b * SEQ * DMODEL);
    uint2* xl = reinterpret_cast<uint2*>(g_Xl + (size_t)b * SEQ * DMODEL);
    const int nvec = SEQ * DMODEL / 4;
    double s = 0.0, q = 0.0;
    for (int i = blockIdx.x * blockDim.x + threadIdx.x; i < nvec;
         i += gridDim.x * blockDim.x) {
        float4 v = xb[i];
        s += (double)v.x; q += (double)v.x * v.x;
        s += (double)v.y; q += (double)v.y * v.y;
        s += (double)v.z; q += (double)v.z * v.z;
        s += (double)v.w; q += (double)v.w * v.w;
        uint32_t h0, l0, h1, l1;
        split2(v.x, v.y, h0, l0);
        split2(v.z, v.w, h1, l1);
        xh[i] = make_uint2(h0, h1);
        xl[i] = make_uint2(l0, l1);
    }
    __shared__ double rs[256], rq[256];
    rs[threadIdx.x] = s; rq[threadIdx.x] = q;
    __syncthreads();
    for (int st = 128; st > 0; st >>= 1) {
        if (threadIdx.x < st) {
            rs[threadIdx.x] += rs[threadIdx.x + st];
            rq[threadIdx.x] += rq[threadIdx.x + st];
        }
        __syncthreads();
    }
    if (threadIdx.x == 0) {
        g_part[(b * NPART + blockIdx.x) * 2 + 0] = rs[0];
        g_part[(b * NPART + blockIdx.x) * 2 + 1] = rq[0];
    }
}

// ================= kernel 2: block 0 = stats/router consts; blocks 1..16 = topo =================
__global__ void k_setup(const int* __restrict__ task_id,
                        const float* __restrict__ task_emb,
                        const float* __restrict__ Wr,
                        const float* __restrict__ br,
                        const float* __restrict__ topo) {
    int tid = threadIdx.x;
    if (blockIdx.x == 0) {
        __shared__ double rd[256];
        for (int b = 0; b < 2; b++) {
            double s = g_part[(b * NPART + tid) * 2 + 0];
            double q = g_part[(b * NPART + tid) * 2 + 1];
            rd[tid] = s; __syncthreads();
            for (int st = 128; st > 0; st >>= 1) {
                if (tid < st) rd[tid] += rd[tid + st];
                __syncthreads();
            }
            double S = rd[0]; __syncthreads();
            rd[tid] = q; __syncthreads();
            for (int st = 128; st > 0; st >>= 1) {
                if (tid < st) rd[tid] += rd[tid + st];
                __syncthreads();
            }
            double Q = rd[0]; __syncthreads();
            if (tid == 0) {
                const double cnt = (double)SEQ * DMODEL;
                double mu  = S / cnt;
                double var = Q / cnt - mu * mu;
                g_stats[b * 2 + 0] = (float)mu;
                g_stats[b * 2 + 1] = (float)(1.0 / sqrt(var + 1e-5));
            }
            __syncthreads();
        }
        {
            __shared__ float rf[256];
            int e = tid & 15, lane = tid >> 4;
            float p = 0.f;
            for (int d = lane; d < DMODEL; d += 16) p += Wr[d * NEXP + e];
            rf[tid] = p; __syncthreads();
            if (tid < 16) {
                float s2 = 0.f;
                for (int l = 0; l < 16; l++) s2 += rf[l * 16 + tid];
                g_cs[tid] = s2;
            }
            __syncthreads();
        }
        if (tid < 32) {
            int b = tid >> 4, e = tid & 15;
            int tI = task_id[b];
            float v = br[e];
            for (int t = 0; t < DTASK; t++)
                v += task_emb[tI * DTASK + t] * Wr[(DMODEL + t) * NEXP + e];
            g_base[b * NEXP + e] = v;
        }
    } else {
        int e = blockIdx.x - 1;
        __shared__ float row[256];
        __shared__ float rs[256];
        row[tid] = topo[e * DBOT + tid];
        __syncthreads();
        float v = row[tid];
        int rank = 0;
#pragma unroll 16
        for (int i = 0; i < DBOT; i++) {
            float u = row[i];
            rank += (u > v) || (u == v && i < tid);
        }
        int sel = (rank < RQUOTA);
        rs[tid] = sel ? 1.f / (1.f + expf(-v)) : 0.f;
        __syncthreads();
        for (int st = 128; st > 0; st >>= 1) {
            if (tid < st) rs[tid] += rs[tid + st];
            __syncthreads();
        }
        float gate = rs[0] / (float)RQUOTA;
        g_gmask[e * DBOT + tid] = sel ? gate : 0.f;
    }
}

// ================= merged transpose + bf16-split of all weights =================
__global__ void k_tsplit(const float* __restrict__ W_down,
                         const float* __restrict__ Wr,
                         const float* __restrict__ W_up) {
    int bid = blockIdx.x;
    const float* in;
    __nv_bfloat16 *outh, *outl;
    int R, C, c0, r0;
    if (bid < 256) {
        in = W_down; outh = g_B1T_h; outl = g_B1T_l;
        R = DMODEL; C = DBOT;
        c0 = (bid & 7) * 32; r0 = (bid >> 3) * 32;
    } else if (bid < 288) {
        in = Wr; outh = g_B1T_h + 256 * DMODEL; outl = g_B1T_l + 256 * DMODEL;
        R = DMODEL; C = NEXP;
        c0 = 0; r0 = (bid - 256) * 32;
    } else {
        in = W_up; outh = g_B2T_h; outl = g_B2T_l;
        R = DBOT; C = DMODEL;
        int idx = bid - 288;
        c0 = (idx & 31) * 32; r0 = (idx >> 5) * 32;
    }

    __shared__ float t[32][33];
    int tx = threadIdx.x, ty = threadIdx.y;
#pragma unroll
    for (int i = 0; i < 32; i += 8) {
        int r = r0 + ty + i, c = c0 + tx;
        t[ty + i][tx] = (r < R && c < C) ? in[(size_t)r * C + c] : 0.f;
    }
    __syncthreads();
#pragma unroll
    for (int i = 0; i < 32; i += 8) {
        int c = c0 + ty + i, r = r0 + tx;
        if (c < C && r < R) {
            float v = t[tx][ty + i];
            __nv_bfloat16 h = __float2bfloat16(v);
            __nv_bfloat16 l = __float2bfloat16(v - __bfloat162float(h));
            outh[(size_t)c * R + r] = h;
            outl[(size_t)c * R + r] = l;
        }
    }
}

// ================= tensor GEMM core: 64x128 CTA tile, 4 warps, 2-stage cp.async =================
// C[row0:+64, n0:+128] = A @ B^T (A [M][K] h/l, B [N][K] h/l)
// smem per stage: Ah[64x64B] Al[64x64B] Bh[128x64B] Bl[128x64B], 16B-chunk XOR swizzle
// MODE 0: plain store (C, ldc). MODE 1: GEMM1 scatter (g_H <256, g_L 256..271)
template <int MODE>
__device__ __forceinline__ void gemm_body(
    const __nv_bfloat16* __restrict__ Ah, const __nv_bfloat16* __restrict__ Al,
    const __nv_bfloat16* __restrict__ Bh, const __nv_bfloat16* __restrict__ Bl,
    int K, int n0, int row0, float* __restrict__ C, int ldc)
{
    extern __shared__ char smem[];
    const int tid = threadIdx.x;
    const int wn = tid >> 5, lane = tid & 31;     // 1x4 warp grid; warp tile 64x32
    const bool active = (MODE == 0) || (n0 + wn * 32 < 272);

    float acc[4][4][4] = {};

    // cp.async fill coords: 32 rows/pass, 4x16B chunks/row
    const int r4 = tid >> 2, j4 = tid & 3;
    const int v4 = (r4 >> 1) & 3;                 // pass-invariant (pass stride 32 rows)
    const uint32_t fill_off = (uint32_t)(r4 * 64 + (j4 ^ v4) * 16);
    const uint32_t sb = smem_u32(smem);

    // ldmatrix logical coords
    const int ra = lane & 15;                     // A row (+ mt*16)
    const int ca = lane >> 4;                     // A 16B chunk (+ 2*ks)
    const int va = (ra >> 1) & 3;                 // mt*16 ≡ 0 mod 4 after >>1&3
    const int rb = wn * 32 + ((lane >> 4) << 3) + (lane & 7);  // B row (+ p*16)
    const int cb = (lane >> 3) & 1;
    const int vb = (rb >> 1) & 3;
    const uint32_t a_base = (uint32_t)(ra * 64);
    const uint32_t b_base = (uint32_t)(rb * 64);

    const int nch = K >> 5;

#define ISSUE(ch) do { \
    const uint32_t _db = sb + ((ch) & 1) * BUFB; \
    const int _k0 = (ch) * 32; \
    _Pragma("unroll") \
    for (int p = 0; p < 2; p++) { \
        uint32_t d = _db + (uint32_t)(p * 2048) + fill_off; \
        size_t ai = (size_t)(row0 + p * 32 + r4) * K + _k0 + j4 * 8; \
        cp16(d, Ah + ai); \
        cp16(d + OFF_AL, Al + ai); \
    } \
    _Pragma("unroll") \
    for (int p = 0; p < 4; p++) { \
        uint32_t d = _db + OFF_BH + (uint32_t)(p * 2048) + fill_off; \
        size_t bi = (size_t)(n0 + p * 32 + r4) * K + _k0 + j4 * 8; \
        cp16(d, Bh + bi); \
        cp16(d + OFF_BD, Bl + bi); \
    } \
    CP_COMMIT(); } while (0)

    ISSUE(0);

    for (int ch = 0; ch < nch; ch++) {
        CP_WAIT(0);
        __syncthreads();             // chunk ch landed AND everyone done with MMA(ch-1)
        if (ch + 1 < nch) ISSUE(ch + 1);   // other buffer (used by ch-1) — safe after sync

        if (active) {
            const uint32_t ab = sb + (ch & 1) * BUFB;
#pragma unroll
            for (int ks = 0; ks < 2; ks++) {
                const uint32_t aoff = ab + a_base + (uint32_t)(((ca + 2 * ks) ^ va) * 16);
                const uint32_t boff = ab + OFF_BH + b_base
                                    + (uint32_t)(((cb + 2 * ks) ^ vb) * 16);
                uint32_t ah[4][4], bb[4][2];
#pragma unroll
                for (int mt = 0; mt < 4; mt++)
                    LDSM4(ah[mt], aoff + mt * 1024);
#pragma unroll
                for (int p = 0; p < 2; p++)
                    LDSM4(&bb[2 * p][0], boff + p * 1024);
                // Ah * Bh
#pragma unroll
                for (int mt = 0; mt < 4; mt++)
#pragma unroll
                    for (int nt = 0; nt < 4; nt++)
                        mma16816(acc[mt][nt], ah[mt], bb[nt]);
                // Al * Bh (reload Al one m-tile at a time)
#pragma unroll
                for (int mt = 0; mt < 4; mt++) {
                    uint32_t al4[4];
                    LDSM4(al4, aoff + OFF_AL + mt * 1024);
#pragma unroll
                    for (int nt = 0; nt < 4; nt++)
                        mma16816(acc[mt][nt], al4, bb[nt]);
                }
                // Ah * Bl
#pragma unroll
                for (int p = 0; p < 2; p++)
                    LDSM4(&bb[2 * p][0], boff + OFF_BD + p * 1024);
#pragma unroll
                for (int mt = 0; mt < 4; mt++)
#pragma unroll
                    for (int nt = 0; nt < 4; nt++)
                        mma16816(acc[mt][nt], ah[mt], bb[nt]);
            }
        }
    }
#undef ISSUE

    if (!active) return;
    const int g = lane >> 2, tig = lane & 3;
#pragma unroll
    for (int mt = 0; mt < 4; mt++) {
        int r = row0 + mt * 16 + g;
#pragma unroll
        for (int nt = 0; nt < 4; nt++) {
            int col = n0 + wn * 32 + nt * 8 + 2 * tig;
            float2 v0 = make_float2(acc[mt][nt][0], acc[mt][nt][1]);
            float2 v1 = make_float2(acc[mt][nt][2], acc[mt][nt][3]);
            if (MODE == 0) {
                *reinterpret_cast<float2*>(&C[(size_t)r * ldc + col]) = v0;
                *reinterpret_cast<float2*>(&C[(size_t)(r + 8) * ldc + col]) = v1;
            } else {
                if (col < DBOT) {
                    *reinterpret_cast<float2*>(&g_H[(size_t)r * DBOT + col]) = v0;
                    *reinterpret_cast<float2*>(&g_H[(size_t)(r + 8) * DBOT + col]) = v1;
                } else if (col < DBOT + NEXP) {
                    int c = col - DBOT;
                    *reinterpret_cast<float2*>(&g_L[(size_t)r * NEXP + c]) = v0;
                    *reinterpret_cast<float2*>(&g_L[(size_t)(r + 8) * NEXP + c]) = v1;
                }
            }
        }
    }
}

__global__ void __launch_bounds__(128, 4) k_gemm1() {
    gemm_body<1>(g_Xh, g_Xl, g_B1T_h, g_B1T_l, DMODEL,
                 blockIdx.x * 128, blockIdx.y * 64, nullptr, 0);
}
__global__ void __launch_bounds__(128, 4) k_gemm2(float* __restrict__ y) {
    gemm_body<0>(g_Zh, g_Zl, g_B2T_h, g_B2T_l, DBOT,
                 blockIdx.x * 128, blockIdx.y * 64, y, DMODEL);
}

// ================= routing (top-2 + softmax) =================
__global__ void k_route() {
    int nIdx = blockIdx.x * blockDim.x + threadIdx.x;
    if (nIdx >= NTOK) return;
    int b = nIdx >> 12;
    float mu = g_stats[b * 2 + 0];
    float rstd = g_stats[b * 2 + 1];
    float best = -1e30f, sec = -1e30f;
    int i0 = 0, i1 = 0;
#pragma unroll
    for (int e = 0; e < NEXP; e++) {
        float l = rstd * (g_L[nIdx * NEXP + e] - mu * g_cs[e]) + g_base[b * NEXP + e];
        if (l > best) { sec = best; i1 = i0; best = l; i0 = e; }
        else if (l > sec) { sec = l; i1 = e; }
    }
    float e1 = expf(sec - best);
    float inv = 1.f / (1.f + e1);
    g_sel[nIdx * 2 + 0] = i0;
    g_sel[nIdx * 2 + 1] = i1;
    g_w[nIdx * 2 + 0] = inv;
    g_w[nIdx * 2 + 1] = e1 * inv;
}

// ================= z = gelu(H) * combine, split to bf16 h/l =================
__global__ void k_z() {
    uint32_t* zh = reinterpret_cast<uint32_t*>(g_Zh);
    uint32_t* zl = reinterpret_cast<uint32_t*>(g_Zl);
    for (int i2 = blockIdx.x * blockDim.x + threadIdx.x; i2 < NTOK * DBOT / 2;
         i2 += gridDim.x * blockDim.x) {
        int idx = i2 * 2;
        int nn = idx >> 8;
        int j = idx & 255;
        float2 hv = *reinterpret_cast<const float2*>(&g_H[idx]);
        float w0 = g_w[nn * 2 + 0], w1 = g_w[nn * 2 + 1];
        const float* m0 = &g_gmask[g_sel[nn * 2 + 0] * DBOT + j];
        const float* m1 = &g_gmask[g_sel[nn * 2 + 1] * DBOT + j];
        float z[2];
#pragma unroll
        for (int t = 0; t < 2; t++) {
            float h = (t == 0) ? hv.x : hv.y;
            float inner = 0.7978845608028654f * (h + 0.044715f * h * h * h);
            float a = 0.5f * h * (1.f + tanhf(inner));
            z[t] = a * (w0 * m0[t] + w1 * m1[t]);
        }
        uint32_t h, l;
        split2(z[0], z[1], h, l);
        zh[i2] = h;
        zl[i2] = l;
    }
}

// ================= launch =================
extern "C" void kernel_launch(void* const* d_in, const int* in_sizes, int n_in,
                              void* d_out, int out_size) {
    const float* x        = (const float*)d_in[0];
    const int*   task_id  = (const int*)d_in[1];
    const float* task_emb = (const float*)d_in[2];
    const float* Wr       = (const float*)d_in[3];
    const float* br       = (const float*)d_in[4];
    const float* W_down   = (const float*)d_in[5];
    const float* W_up     = (const float*)d_in[6];
    const float* topo     = (const float*)d_in[7];
    float* y = (float*)d_out;

    cudaFuncSetAttribute(k_gemm1, cudaFuncAttributeMaxDynamicSharedMemorySize, NSTG * BUFB);
    cudaFuncSetAttribute(k_gemm2, cudaFuncAttributeMaxDynamicSharedMemorySize, NSTG * BUFB);

    k_stats<<<dim3(NPART, 2), 256>>>(x);
    k_setup<<<17, 256>>>(task_id, task_emb, Wr, br, topo);
    k_tsplit<<<544, dim3(32, 8)>>>(W_down, Wr, W_up);
    k_gemm1<<<dim3(3, 128), 128, NSTG * BUFB>>>();   // launch #4 -> profiled
    k_route<<<32, 256>>>();
    k_z<<<1024, 256>>>();
    k_gemm2<<<dim3(8, 128), 128, NSTG * BUFB>>>(y);
}